// round 14
// baseline (speedup 1.0000x reference)
#include <cuda_runtime.h>
#include <cuda_fp16.h>
#include <cstdint>

#define NROWS 8192
#define D_FIX 256
#define KEXT  768             // 3 segments of 256: hh, hm, mh
#define EPSF  1e-12f

// ---------------- scratch (static device arrays; no runtime allocation) ----
__device__ float g_sim[(size_t)NROWS * (size_t)NROWS];          // 256 MB
__device__ __align__(16) __half g_xa[(size_t)NROWS * KEXT];     // 12.6 MB
__device__ __align__(16) __half g_xb[(size_t)NROWS * KEXT];     // 12.6 MB
__device__ float g_x2[NROWS], g_xn2[NROWS];
__device__ float g_k[NROWS], g_t[NROWS];
__device__ unsigned int g_rminu[NROWS], g_rmaxu[NROWS];
__device__ unsigned int g_cnt[64];        // row-block tile-completion counters
__device__ unsigned int g_echunk[64];     // row-block epilogue chunk claim counters
__device__ unsigned int g_done;           // CTA retirement counter

// monotone float<->uint key
__device__ __forceinline__ unsigned int fkey(float f) {
    unsigned int b = __float_as_uint(f);
    return (b & 0x80000000u) ? ~b : (b | 0x80000000u);
}
__device__ __forceinline__ float funkey(unsigned int u) {
    return __uint_as_float((u & 0x80000000u) ? (u & 0x7FFFFFFFu) : ~u);
}

// ---------------- prep: fp16 2-way split + row norms + sigmoid head --------
// A segments: [h | h | m],  B segments: [h | m | h]
// Also resets min/max identities, block counters, chunk counters, done counter.
__global__ void prep_x_kernel(const float* __restrict__ x,
                              const float* __restrict__ W,
                              const float* __restrict__ b, int N) {
    int row  = blockIdx.x * 8 + (threadIdx.x >> 5);
    int lane = threadIdx.x & 31;
    if (row >= N) return;
    const float* xr = x + (size_t)row * D_FIX;
    float s2 = 0.f, p0 = 0.f, p1 = 0.f;
#pragma unroll
    for (int c = lane * 4; c < D_FIX; c += 128) {
        float4 v = *(const float4*)(xr + c);
        s2 += v.x * v.x + v.y * v.y + v.z * v.z + v.w * v.w;
        p0 += v.x * W[2*c + 0] + v.y * W[2*c + 2] + v.z * W[2*c + 4] + v.w * W[2*c + 6];
        p1 += v.x * W[2*c + 1] + v.y * W[2*c + 3] + v.z * W[2*c + 5] + v.w * W[2*c + 7];
        float f[4] = {v.x, v.y, v.z, v.w};
        size_t o = (size_t)row * KEXT + c;
#pragma unroll
        for (int q = 0; q < 4; q++) {
            __half h = __float2half_rn(f[q]);
            __half m = __float2half_rn(f[q] - __half2float(h));
            g_xa[o + q]       = h;
            g_xa[o + q + 256] = h;
            g_xa[o + q + 512] = m;
        }
    }
#pragma unroll
    for (int off = 16; off; off >>= 1) {
        s2 += __shfl_xor_sync(0xffffffffu, s2, off);
        p0 += __shfl_xor_sync(0xffffffffu, p0, off);
        p1 += __shfl_xor_sync(0xffffffffu, p1, off);
    }
    if (lane == 0) {
        g_x2[row] = s2;
        float kk = 1.f / (1.f + expf(-(p0 + b[0])));
        float tt = 1.f / (1.f + expf(-(p1 + b[1])));
        g_k[row] = fminf(fmaxf(kk, EPSF), 1.f - EPSF);
        g_t[row] = fminf(fmaxf(tt, EPSF), 1.f - EPSF);
    }
    if (lane == 1) g_rminu[row] = 0xFFFFFFFFu;
    if (lane == 2) g_rmaxu[row] = 0u;
    if (lane == 3 && row < 64) g_cnt[row] = 0u;
    if (lane == 4 && row < 64) g_echunk[row] = 0u;
    if (lane == 5 && row == 0) g_done = 0u;
}

__global__ void prep_xn_kernel(const float* __restrict__ xn, int M) {
    int row  = blockIdx.x * 8 + (threadIdx.x >> 5);
    int lane = threadIdx.x & 31;
    if (row >= M) return;
    const float* xr = xn + (size_t)row * D_FIX;
    float s2 = 0.f;
#pragma unroll
    for (int c = lane * 4; c < D_FIX; c += 128) {
        float4 v = *(const float4*)(xr + c);
        s2 += v.x * v.x + v.y * v.y + v.z * v.z + v.w * v.w;
        float f[4] = {v.x, v.y, v.z, v.w};
        size_t o = (size_t)row * KEXT + c;
#pragma unroll
        for (int q = 0; q < 4; q++) {
            __half h = __float2half_rn(f[q]);
            __half m = __float2half_rn(f[q] - __half2float(h));
            g_xb[o + q]       = h;
            g_xb[o + q + 256] = m;
            g_xb[o + q + 512] = h;
        }
    }
#pragma unroll
    for (int off = 16; off; off >>= 1)
        s2 += __shfl_xor_sync(0xffffffffu, s2, off);
    if (lane == 0) g_xn2[row] = s2;
}

// ---------------- fp16 mma.sync GEMM + work-stealing epilogue ---------------
#define BM 128
#define BN 128
#define BK 64
#define SST 72
#define ATILE_B (BM * SST * 2)          // 18432 bytes per operand buffer
#define BUF_B   (2 * ATILE_B)           // A + B per stage = 36864
#define NSTAGE  3
#define SMEM_TOT (NSTAGE * BUF_B)       // 110592
#define NCH (KEXT / BK)                 // 12
#define NCHUNKS 32                      // epilogue chunks per row-block (256 cols each)

__device__ __forceinline__ void ldsm_x4(uint32_t* r, uint32_t addr) {
    asm volatile("ldmatrix.sync.aligned.m8n8.x4.shared.b16 {%0,%1,%2,%3}, [%4];"
                 : "=r"(r[0]), "=r"(r[1]), "=r"(r[2]), "=r"(r[3]) : "r"(addr));
}

__device__ __forceinline__ void mma_f16(float* c, const uint32_t* a,
                                        uint32_t b0, uint32_t b1) {
    asm volatile(
        "mma.sync.aligned.m16n8k16.row.col.f32.f16.f16.f32 "
        "{%0,%1,%2,%3}, {%4,%5,%6,%7}, {%8,%9}, {%0,%1,%2,%3};"
        : "+f"(c[0]), "+f"(c[1]), "+f"(c[2]), "+f"(c[3])
        : "r"(a[0]), "r"(a[1]), "r"(a[2]), "r"(a[3]), "r"(b0), "r"(b1));
}

__device__ __forceinline__ void cp16(uint32_t dst, const void* src) {
    asm volatile("cp.async.cg.shared.global [%0], [%1], 16;"
                 :: "r"(dst), "l"(src) : "memory");
}
__device__ __forceinline__ void cp_commit() {
    asm volatile("cp.async.commit_group;" ::: "memory");
}
template <int Nw>
__device__ __forceinline__ void cp_wait() {
    asm volatile("cp.async.wait_group %0;" :: "n"(Nw) : "memory");
}

__device__ __forceinline__ float sknn_fast(float v, float mn, float inv,
                                           float k, float alpha, float logk) {
    float s = fmaxf((v - mn) * inv, EPSF);
    return s + ((s <= k) ? alpha * (k - s) * (__logf(s) - logk) : 0.f);
}

// normalize one chunk: rows [rb*128, rb*128+128), cols [ch*256, ch*256+256)
__device__ void process_chunk(int rb, int ch, float* __restrict__ outp,
                               int M, int tid) {
    const int warp = tid >> 5;
    const int lane = tid & 31;
    const int col0 = ch * 256 + lane * 8;
#pragma unroll 1
    for (int rr = warp; rr < BM; rr += 8) {
        const int row = rb * BM + rr;
        const float k    = g_k[row];
        const float t    = g_t[row];
        const float mn   = funkey(g_rminu[row]);
        const float inv  = 1.f / (funkey(g_rmaxu[row]) - mn);
        const float alpha = t / (1.f - t);
        const float logk  = __logf(k);
        const float* src = g_sim + (size_t)row * M + col0;
        float*       dst = outp  + (size_t)row * M + col0;
        float4 v0 = *(const float4*)(src);
        float4 v1 = *(const float4*)(src + 4);
        float4 o0, o1;
        o0.x = sknn_fast(v0.x, mn, inv, k, alpha, logk);
        o0.y = sknn_fast(v0.y, mn, inv, k, alpha, logk);
        o0.z = sknn_fast(v0.z, mn, inv, k, alpha, logk);
        o0.w = sknn_fast(v0.w, mn, inv, k, alpha, logk);
        o1.x = sknn_fast(v1.x, mn, inv, k, alpha, logk);
        o1.y = sknn_fast(v1.y, mn, inv, k, alpha, logk);
        o1.z = sknn_fast(v1.z, mn, inv, k, alpha, logk);
        o1.w = sknn_fast(v1.w, mn, inv, k, alpha, logk);
        *(float4*)(dst)     = o0;
        *(float4*)(dst + 4) = o1;
    }
}

__global__ void __launch_bounds__(256, 2) gemm_sim_kernel(float* __restrict__ outp,
                                                          int M) {
    extern __shared__ __align__(16) char dsm[];
    const uint32_t sbase = (uint32_t)__cvta_generic_to_shared(dsm);

    const int tid  = threadIdx.x;
    const int lane = tid & 31;
    const int warp = tid >> 5;
    const int wm   = warp >> 1;   // 0..3
    const int wn   = warp & 1;    // 0..1
    const int rowbase = blockIdx.y * BM;
    const int colbase = blockIdx.x * BN;

    float acc[2][8][4];
#pragma unroll
    for (int i = 0; i < 2; i++)
#pragma unroll
        for (int j = 0; j < 8; j++)
#pragma unroll
            for (int q = 0; q < 4; q++) acc[i][j][q] = 0.f;

    const int ldr = tid >> 3;          // 0..31
    const int ldc = (tid & 7) * 8;     // half column (8 per uint4)

    const __half* gA = g_xa + (size_t)(rowbase + ldr) * KEXT + ldc;
    const __half* gB = g_xb + (size_t)(colbase + ldr) * KEXT + ldc;
    const uint32_t dA = sbase + (ldr * SST + ldc) * 2;             // + stage*BUF_B
    const uint32_t dB = dA + ATILE_B;

    const uint32_t aAddr0 = sbase + (uint32_t)(((wm * 32 + (lane & 15)) * SST
                                                + (lane >> 4) * 8) * 2);
    const uint32_t bAddr0 = sbase + ATILE_B
                          + (uint32_t)(((wn * 64 + (lane & 15)) * SST
                                        + (lane >> 4) * 8) * 2);

    // prologue: issue chunks 0 and 1
#pragma unroll
    for (int s = 0; s < 2; s++) {
        const uint32_t so = (uint32_t)s * BUF_B;
#pragma unroll
        for (int p = 0; p < 4; p++) {
            cp16(dA + so + p * 32 * SST * 2, gA + (size_t)(p * 32) * KEXT + s * BK);
            cp16(dB + so + p * 32 * SST * 2, gB + (size_t)(p * 32) * KEXT + s * BK);
        }
        cp_commit();
    }

#pragma unroll 1
    for (int kc = 0; kc < NCH; kc++) {
        const uint32_t so = (uint32_t)(kc % NSTAGE) * BUF_B;
        if (kc + 1 < NCH) cp_wait<1>(); else cp_wait<0>();
        __syncthreads();

        if (kc + 2 < NCH) {
            const uint32_t ns = (uint32_t)((kc + 2) % NSTAGE) * BUF_B;
            const int koff = (kc + 2) * BK;
#pragma unroll
            for (int p = 0; p < 4; p++) {
                cp16(dA + ns + p * 32 * SST * 2, gA + (size_t)(p * 32) * KEXT + koff);
                cp16(dB + ns + p * 32 * SST * 2, gB + (size_t)(p * 32) * KEXT + koff);
            }
            cp_commit();
        }

#pragma unroll
        for (int ks = 0; ks < 4; ks++) {
            uint32_t a[2][4], bb[4][4];
            const uint32_t ak = aAddr0 + so + ks * 32;   // ks*16 halfs
            const uint32_t bk = bAddr0 + so + ks * 32;
            ldsm_x4(a[0], ak);
            ldsm_x4(a[1], ak + (uint32_t)(16 * SST * 2));
#pragma unroll
            for (int nj = 0; nj < 4; nj++)
                ldsm_x4(bb[nj], bk + (uint32_t)(nj * 16 * SST * 2));
#pragma unroll
            for (int nj = 0; nj < 4; nj++) {
#pragma unroll
                for (int mi = 0; mi < 2; mi++) {
                    mma_f16(acc[mi][2 * nj + 0], a[mi], bb[nj][0], bb[nj][2]);
                    mma_f16(acc[mi][2 * nj + 1], a[mi], bb[nj][1], bb[nj][3]);
                }
            }
        }
    }

    // tile epilogue: sim = -sqrt(max(x2+xn2-2*dot,0)) -> scratch + row min/max
#pragma unroll
    for (int mi = 0; mi < 2; mi++) {
        int r0 = rowbase + wm * 32 + mi * 16 + (lane >> 2);
        int r1 = r0 + 8;
        float xa = g_x2[r0];
        float xb = g_x2[r1];
        float mn0 = 3.4e38f, mx0 = -3.4e38f;
        float mn1 = 3.4e38f, mx1 = -3.4e38f;
#pragma unroll
        for (int nj8 = 0; nj8 < 8; nj8++) {
            int c0 = colbase + wn * 64 + nj8 * 8 + (lane & 3) * 2;
            float y0 = g_xn2[c0];
            float y1 = g_xn2[c0 + 1];
            float2 s0, s1;
            s0.x = -sqrtf(fmaxf(xa + y0 - 2.f * acc[mi][nj8][0], 0.f));
            s0.y = -sqrtf(fmaxf(xa + y1 - 2.f * acc[mi][nj8][1], 0.f));
            s1.x = -sqrtf(fmaxf(xb + y0 - 2.f * acc[mi][nj8][2], 0.f));
            s1.y = -sqrtf(fmaxf(xb + y1 - 2.f * acc[mi][nj8][3], 0.f));
            *(float2*)(g_sim + (size_t)r0 * M + c0) = s0;
            *(float2*)(g_sim + (size_t)r1 * M + c0) = s1;
            mn0 = fminf(mn0, fminf(s0.x, s0.y));
            mx0 = fmaxf(mx0, fmaxf(s0.x, s0.y));
            mn1 = fminf(mn1, fminf(s1.x, s1.y));
            mx1 = fmaxf(mx1, fmaxf(s1.x, s1.y));
        }
#pragma unroll
        for (int off = 1; off < 4; off <<= 1) {
            mn0 = fminf(mn0, __shfl_xor_sync(0xffffffffu, mn0, off));
            mx0 = fmaxf(mx0, __shfl_xor_sync(0xffffffffu, mx0, off));
            mn1 = fminf(mn1, __shfl_xor_sync(0xffffffffu, mn1, off));
            mx1 = fmaxf(mx1, __shfl_xor_sync(0xffffffffu, mx1, off));
        }
        if ((lane & 3) == 0) {
            atomicMin(&g_rminu[r0], fkey(mn0));
            atomicMax(&g_rmaxu[r0], fkey(mx0));
            atomicMin(&g_rminu[r1], fkey(mn1));
            atomicMax(&g_rmaxu[r1], fkey(mx1));
        }
    }

    // ---- cooperative work-stealing epilogue over completed row-blocks ------
    __threadfence();
    __syncthreads();
    if (tid == 0) atomicAdd(&g_cnt[blockIdx.y], 1u);

    __shared__ int sh_flag;
    __shared__ unsigned int sh_chunk;

    // single pass over row-blocks: claim chunks of any completed block, no spin
#pragma unroll 1
    for (int rb = 0; rb < 64; rb++) {
        __syncthreads();
        if (tid == 0) sh_flag = (atomicAdd(&g_cnt[rb], 0u) >= 64u) ? 1 : 0;
        __syncthreads();
        if (!sh_flag) continue;
#pragma unroll 1
        for (;;) {
            if (tid == 0) sh_chunk = atomicAdd(&g_echunk[rb], 1u);
            __syncthreads();
            unsigned int ch = sh_chunk;
            __syncthreads();
            if (ch >= NCHUNKS) break;
            __threadfence();   // acquire: other CTAs' sim/minmax writes
            process_chunk(rb, (int)ch, outp, M, tid);
        }
    }

    // last CTA to retire drains all remaining chunks (exact conservation)
    __syncthreads();
    __threadfence();
    if (tid == 0)
        sh_flag = (atomicAdd(&g_done, 1u) ==
                   (unsigned)(gridDim.x * gridDim.y - 1)) ? 1 : 0;
    __syncthreads();
    if (sh_flag) {
#pragma unroll 1
        for (int rb = 0; rb < 64; rb++) {
#pragma unroll 1
            for (;;) {
                if (tid == 0) sh_chunk = atomicAdd(&g_echunk[rb], 1u);
                __syncthreads();
                unsigned int ch = sh_chunk;
                __syncthreads();
                if (ch >= NCHUNKS) break;
                __threadfence();
                process_chunk(rb, (int)ch, outp, M, tid);
            }
        }
    }
}

// ---------------- launcher ---------------------------------------------------
extern "C" void kernel_launch(void* const* d_in, const int* in_sizes, int n_in,
                              void* d_out, int out_size) {
    const float* x  = (const float*)d_in[0];
    const float* xn = (const float*)d_in[1];
    const float* W  = (const float*)d_in[2];
    const float* b  = (const float*)d_in[3];
    float* out = (float*)d_out;

    int D = in_sizes[2] / 2;            // 256
    int N = in_sizes[0] / D;            // 8192
    int M = in_sizes[1] / D;            // 8192

    cudaFuncSetAttribute(gemm_sim_kernel,
                         cudaFuncAttributeMaxDynamicSharedMemorySize, SMEM_TOT);

    prep_x_kernel <<<(N + 7) / 8, 256>>>(x, W, b, N);
    prep_xn_kernel<<<(M + 7) / 8, 256>>>(xn, M);

    dim3 gg(M / BN, N / BM);
    gemm_sim_kernel<<<gg, 256, SMEM_TOT>>>(out, M);
}

// round 15
// speedup vs baseline: 2.1508x; 2.1508x over previous
#include <cuda_runtime.h>
#include <cuda_fp16.h>
#include <cstdint>

#define NROWS 8192
#define D_FIX 256
#define KEXT  768             // 3 segments of 256: hh, hm, mh
#define EPSF  1e-12f

// ---------------- scratch (static device arrays; no runtime allocation) ----
__device__ float g_sim[(size_t)NROWS * (size_t)NROWS];          // 256 MB
__device__ __align__(16) __half g_xa[(size_t)NROWS * KEXT];     // 12.6 MB
__device__ __align__(16) __half g_xb[(size_t)NROWS * KEXT];     // 12.6 MB
__device__ float g_x2[NROWS], g_xn2[NROWS];
__device__ float g_k[NROWS], g_t[NROWS];
__device__ unsigned int g_rminu[NROWS], g_rmaxu[NROWS];

// monotone float<->uint key
__device__ __forceinline__ unsigned int fkey(float f) {
    unsigned int b = __float_as_uint(f);
    return (b & 0x80000000u) ? ~b : (b | 0x80000000u);
}
__device__ __forceinline__ float funkey(unsigned int u) {
    return __uint_as_float((u & 0x80000000u) ? (u & 0x7FFFFFFFu) : ~u);
}

// ---------------- merged prep: both operands in one launch -------------------
// blocks [0, N/8)          : x  -> norms, head, A=[h|h|m], minmax init
// blocks [N/8, N/8 + M/8)  : xn -> norms,       B=[h|m|h]
__global__ void prep_kernel(const float* __restrict__ x,
                            const float* __restrict__ xn,
                            const float* __restrict__ W,
                            const float* __restrict__ b, int N, int M) {
    const int nxblocks = N / 8;
    const bool isX = (int)blockIdx.x < nxblocks;
    int row  = (isX ? blockIdx.x : blockIdx.x - nxblocks) * 8 + (threadIdx.x >> 5);
    int lane = threadIdx.x & 31;

    if (isX) {
        if (row >= N) return;
        const float* xr = x + (size_t)row * D_FIX;
        float s2 = 0.f, p0 = 0.f, p1 = 0.f;
#pragma unroll
        for (int c = lane * 4; c < D_FIX; c += 128) {
            float4 v = *(const float4*)(xr + c);
            s2 += v.x * v.x + v.y * v.y + v.z * v.z + v.w * v.w;
            p0 += v.x * W[2*c + 0] + v.y * W[2*c + 2] + v.z * W[2*c + 4] + v.w * W[2*c + 6];
            p1 += v.x * W[2*c + 1] + v.y * W[2*c + 3] + v.z * W[2*c + 5] + v.w * W[2*c + 7];
            float f[4] = {v.x, v.y, v.z, v.w};
            size_t o = (size_t)row * KEXT + c;
#pragma unroll
            for (int q = 0; q < 4; q++) {
                __half h = __float2half_rn(f[q]);
                __half m = __float2half_rn(f[q] - __half2float(h));
                g_xa[o + q]       = h;
                g_xa[o + q + 256] = h;
                g_xa[o + q + 512] = m;
            }
        }
#pragma unroll
        for (int off = 16; off; off >>= 1) {
            s2 += __shfl_xor_sync(0xffffffffu, s2, off);
            p0 += __shfl_xor_sync(0xffffffffu, p0, off);
            p1 += __shfl_xor_sync(0xffffffffu, p1, off);
        }
        if (lane == 0) {
            g_x2[row] = s2;
            float kk = 1.f / (1.f + expf(-(p0 + b[0])));
            float tt = 1.f / (1.f + expf(-(p1 + b[1])));
            g_k[row] = fminf(fmaxf(kk, EPSF), 1.f - EPSF);
            g_t[row] = fminf(fmaxf(tt, EPSF), 1.f - EPSF);
        }
        if (lane == 1) g_rminu[row] = 0xFFFFFFFFu;
        if (lane == 2) g_rmaxu[row] = 0u;
    } else {
        if (row >= M) return;
        const float* xr = xn + (size_t)row * D_FIX;
        float s2 = 0.f;
#pragma unroll
        for (int c = lane * 4; c < D_FIX; c += 128) {
            float4 v = *(const float4*)(xr + c);
            s2 += v.x * v.x + v.y * v.y + v.z * v.z + v.w * v.w;
            float f[4] = {v.x, v.y, v.z, v.w};
            size_t o = (size_t)row * KEXT + c;
#pragma unroll
            for (int q = 0; q < 4; q++) {
                __half h = __float2half_rn(f[q]);
                __half m = __float2half_rn(f[q] - __half2float(h));
                g_xb[o + q]       = h;
                g_xb[o + q + 256] = m;
                g_xb[o + q + 512] = h;
            }
        }
#pragma unroll
        for (int off = 16; off; off >>= 1)
            s2 += __shfl_xor_sync(0xffffffffu, s2, off);
        if (lane == 0) g_xn2[row] = s2;
    }
}

// ---------------- fp16 mma.sync GEMM, 3-stage pipeline, 1 barrier/chunk -----
#define BM 128
#define BN 128
#define BK 64
#define SST 72
#define ATILE_B (BM * SST * 2)          // 18432 bytes per operand buffer
#define BUF_B   (2 * ATILE_B)           // A + B per stage = 36864
#define NSTAGE  3
#define SMEM_TOT (NSTAGE * BUF_B)       // 110592
#define NCH (KEXT / BK)                 // 12

__device__ __forceinline__ void ldsm_x4(uint32_t* r, uint32_t addr) {
    asm volatile("ldmatrix.sync.aligned.m8n8.x4.shared.b16 {%0,%1,%2,%3}, [%4];"
                 : "=r"(r[0]), "=r"(r[1]), "=r"(r[2]), "=r"(r[3]) : "r"(addr));
}

__device__ __forceinline__ void mma_f16(float* c, const uint32_t* a,
                                        uint32_t b0, uint32_t b1) {
    asm volatile(
        "mma.sync.aligned.m16n8k16.row.col.f32.f16.f16.f32 "
        "{%0,%1,%2,%3}, {%4,%5,%6,%7}, {%8,%9}, {%0,%1,%2,%3};"
        : "+f"(c[0]), "+f"(c[1]), "+f"(c[2]), "+f"(c[3])
        : "r"(a[0]), "r"(a[1]), "r"(a[2]), "r"(a[3]), "r"(b0), "r"(b1));
}

__device__ __forceinline__ void cp16(uint32_t dst, const void* src) {
    asm volatile("cp.async.cg.shared.global [%0], [%1], 16;"
                 :: "r"(dst), "l"(src) : "memory");
}
__device__ __forceinline__ void cp_commit() {
    asm volatile("cp.async.commit_group;" ::: "memory");
}
template <int Nw>
__device__ __forceinline__ void cp_wait() {
    asm volatile("cp.async.wait_group %0;" :: "n"(Nw) : "memory");
}

__global__ void __launch_bounds__(256, 2) gemm_sim_kernel(int M) {
    extern __shared__ __align__(16) char dsm[];
    const uint32_t sbase = (uint32_t)__cvta_generic_to_shared(dsm);

    const int tid  = threadIdx.x;
    const int lane = tid & 31;
    const int warp = tid >> 5;
    const int wm   = warp >> 1;   // 0..3
    const int wn   = warp & 1;    // 0..1
    const int rowbase = blockIdx.y * BM;
    const int colbase = blockIdx.x * BN;

    float acc[2][8][4];
#pragma unroll
    for (int i = 0; i < 2; i++)
#pragma unroll
        for (int j = 0; j < 8; j++)
#pragma unroll
            for (int q = 0; q < 4; q++) acc[i][j][q] = 0.f;

    const int ldr = tid >> 3;          // 0..31
    const int ldc = (tid & 7) * 8;     // half column (8 per uint4)

    const __half* gA = g_xa + (size_t)(rowbase + ldr) * KEXT + ldc;
    const __half* gB = g_xb + (size_t)(colbase + ldr) * KEXT + ldc;
    const uint32_t dA = sbase + (ldr * SST + ldc) * 2;             // + stage*BUF_B
    const uint32_t dB = dA + ATILE_B;

    const uint32_t aAddr0 = sbase + (uint32_t)(((wm * 32 + (lane & 15)) * SST
                                                + (lane >> 4) * 8) * 2);
    const uint32_t bAddr0 = sbase + ATILE_B
                          + (uint32_t)(((wn * 64 + (lane & 15)) * SST
                                        + (lane >> 4) * 8) * 2);

    // prologue: issue chunks 0 and 1
#pragma unroll
    for (int s = 0; s < 2; s++) {
        const uint32_t so = (uint32_t)s * BUF_B;
#pragma unroll
        for (int p = 0; p < 4; p++) {
            cp16(dA + so + p * 32 * SST * 2, gA + (size_t)(p * 32) * KEXT + s * BK);
            cp16(dB + so + p * 32 * SST * 2, gB + (size_t)(p * 32) * KEXT + s * BK);
        }
        cp_commit();
    }

    // single barrier per chunk: at barrier(kc), all warps finished compute
    // kc-1, the only reader of stage (kc+2)%3 == (kc-1)%3 -> safe to prefetch.
#pragma unroll 1
    for (int kc = 0; kc < NCH; kc++) {
        const uint32_t so = (uint32_t)(kc % NSTAGE) * BUF_B;
        if (kc + 1 < NCH) cp_wait<1>(); else cp_wait<0>();
        __syncthreads();

        if (kc + 2 < NCH) {
            const uint32_t ns = (uint32_t)((kc + 2) % NSTAGE) * BUF_B;
            const int koff = (kc + 2) * BK;
#pragma unroll
            for (int p = 0; p < 4; p++) {
                cp16(dA + ns + p * 32 * SST * 2, gA + (size_t)(p * 32) * KEXT + koff);
                cp16(dB + ns + p * 32 * SST * 2, gB + (size_t)(p * 32) * KEXT + koff);
            }
            cp_commit();
        }

#pragma unroll
        for (int ks = 0; ks < 4; ks++) {
            uint32_t a[2][4], bb[4][4];
            const uint32_t ak = aAddr0 + so + ks * 32;   // ks*16 halfs
            const uint32_t bk = bAddr0 + so + ks * 32;
            ldsm_x4(a[0], ak);
            ldsm_x4(a[1], ak + (uint32_t)(16 * SST * 2));
#pragma unroll
            for (int nj = 0; nj < 4; nj++)
                ldsm_x4(bb[nj], bk + (uint32_t)(nj * 16 * SST * 2));
#pragma unroll
            for (int nj = 0; nj < 4; nj++) {
#pragma unroll
                for (int mi = 0; mi < 2; mi++) {
                    mma_f16(acc[mi][2 * nj + 0], a[mi], bb[nj][0], bb[nj][2]);
                    mma_f16(acc[mi][2 * nj + 1], a[mi], bb[nj][1], bb[nj][3]);
                }
            }
        }
    }

    // epilogue: sim = -sqrt(max(x2+xn2-2*dot,0)) -> scratch, fused row min/max
#pragma unroll
    for (int mi = 0; mi < 2; mi++) {
        int r0 = rowbase + wm * 32 + mi * 16 + (lane >> 2);
        int r1 = r0 + 8;
        float xa = g_x2[r0];
        float xb = g_x2[r1];
        float mn0 = 3.4e38f, mx0 = -3.4e38f;
        float mn1 = 3.4e38f, mx1 = -3.4e38f;
#pragma unroll
        for (int nj8 = 0; nj8 < 8; nj8++) {
            int c0 = colbase + wn * 64 + nj8 * 8 + (lane & 3) * 2;
            float y0 = g_xn2[c0];
            float y1 = g_xn2[c0 + 1];
            float2 s0, s1;
            s0.x = -sqrtf(fmaxf(xa + y0 - 2.f * acc[mi][nj8][0], 0.f));
            s0.y = -sqrtf(fmaxf(xa + y1 - 2.f * acc[mi][nj8][1], 0.f));
            s1.x = -sqrtf(fmaxf(xb + y0 - 2.f * acc[mi][nj8][2], 0.f));
            s1.y = -sqrtf(fmaxf(xb + y1 - 2.f * acc[mi][nj8][3], 0.f));
            *(float2*)(g_sim + (size_t)r0 * M + c0) = s0;
            *(float2*)(g_sim + (size_t)r1 * M + c0) = s1;
            mn0 = fminf(mn0, fminf(s0.x, s0.y));
            mx0 = fmaxf(mx0, fmaxf(s0.x, s0.y));
            mn1 = fminf(mn1, fminf(s1.x, s1.y));
            mx1 = fmaxf(mx1, fmaxf(s1.x, s1.y));
        }
#pragma unroll
        for (int off = 1; off < 4; off <<= 1) {
            mn0 = fminf(mn0, __shfl_xor_sync(0xffffffffu, mn0, off));
            mx0 = fmaxf(mx0, __shfl_xor_sync(0xffffffffu, mx0, off));
            mn1 = fminf(mn1, __shfl_xor_sync(0xffffffffu, mn1, off));
            mx1 = fmaxf(mx1, __shfl_xor_sync(0xffffffffu, mx1, off));
        }
        if ((lane & 3) == 0) {
            atomicMin(&g_rminu[r0], fkey(mn0));
            atomicMax(&g_rmaxu[r0], fkey(mx0));
            atomicMin(&g_rminu[r1], fkey(mn1));
            atomicMax(&g_rmaxu[r1], fkey(mx1));
        }
    }
}

// ---------------- normalize + soft-KNN shift (16 elems/thread) --------------
__device__ __forceinline__ float sknn_fast(float v, float mn, float inv,
                                           float k, float alpha, float logk) {
    float s = fmaxf((v - mn) * inv, EPSF);
    return s + ((s <= k) ? alpha * (k - s) * (__logf(s) - logk) : 0.f);
}

__global__ void epilogue_kernel(float* __restrict__ out, int M) {
    int row = blockIdx.y;
    int c = (blockIdx.x * blockDim.x + threadIdx.x) * 16;
    if (c >= M) return;
    float k    = g_k[row];
    float t    = g_t[row];
    float mn   = funkey(g_rminu[row]);
    float mx   = funkey(g_rmaxu[row]);
    float inv  = 1.f / (mx - mn);
    float alpha = t / (1.f - t);
    float logk = __logf(k);
    const float* src = g_sim + (size_t)row * M + c;
    float*       dst = out   + (size_t)row * M + c;
    float4 v[4];
#pragma unroll
    for (int q = 0; q < 4; q++) v[q] = *(const float4*)(src + q * 4);
#pragma unroll
    for (int q = 0; q < 4; q++) {
        float4 o;
        o.x = sknn_fast(v[q].x, mn, inv, k, alpha, logk);
        o.y = sknn_fast(v[q].y, mn, inv, k, alpha, logk);
        o.z = sknn_fast(v[q].z, mn, inv, k, alpha, logk);
        o.w = sknn_fast(v[q].w, mn, inv, k, alpha, logk);
        *(float4*)(dst + q * 4) = o;
    }
}

// ---------------- launcher ---------------------------------------------------
extern "C" void kernel_launch(void* const* d_in, const int* in_sizes, int n_in,
                              void* d_out, int out_size) {
    const float* x  = (const float*)d_in[0];
    const float* xn = (const float*)d_in[1];
    const float* W  = (const float*)d_in[2];
    const float* b  = (const float*)d_in[3];
    float* out = (float*)d_out;

    int D = in_sizes[2] / 2;            // 256
    int N = in_sizes[0] / D;            // 8192
    int M = in_sizes[1] / D;            // 8192

    cudaFuncSetAttribute(gemm_sim_kernel,
                         cudaFuncAttributeMaxDynamicSharedMemorySize, SMEM_TOT);

    prep_kernel<<<(N + 7) / 8 + (M + 7) / 8, 256>>>(x, xn, W, b, N, M);

    dim3 gg(M / BN, N / BM);
    gemm_sim_kernel<<<gg, 256, SMEM_TOT>>>(M);

    dim3 ge((M / 16 + 255) / 256, N);
    epilogue_kernel<<<ge, 256>>>(out, M);
}